// round 2
// baseline (speedup 1.0000x reference)
#include <cuda_runtime.h>
#include <cstdint>

#define DIM 64
#define CHUNKS 16   // float4 chunks per row (64 floats / 4)

// 0 = indices are int32, 1 = indices are int64
__device__ int g_idx64;

// ---------------------------------------------------------------------------
// probe: decide index width from bit pattern of src0.
// int64 values in [0,1e5): odd 32-bit words are always 0 (high halves).
// int32 random values: P(4 specific words == 0) ~ 1e-20.
// Deterministic per input.
// ---------------------------------------------------------------------------
__global__ void probe_kernel(const unsigned int* __restrict__ s0_words) {
    if (threadIdx.x == 0 && blockIdx.x == 0) {
        bool i64 = (s0_words[1] == 0u) && (s0_words[3] == 0u) &&
                   (s0_words[5] == 0u) && (s0_words[7] == 0u);
        g_idx64 = i64 ? 1 : 0;
    }
}

__device__ __forceinline__ long long load_idx(const void* p, int i, int idx64) {
    if (idx64)
        return ((const long long*)p)[i];
    else
        return (long long)((const int*)p)[i];
}

// ---------------------------------------------------------------------------
// zero the output accumulator
// ---------------------------------------------------------------------------
__global__ void zero_kernel(float4* __restrict__ out, int n4) {
    int i = blockIdx.x * blockDim.x + threadIdx.x;
    if (i < n4) out[i] = make_float4(0.f, 0.f, 0.f, 0.f);
}

// ---------------------------------------------------------------------------
// gather + scatter-add. One thread = one (edge, float4-chunk).
// gridDim.y = relation id (0..3):
//   rel 0: embed0[src0] += into h_B  (out + N*D)
//   rel 1: embed1[src1] += into h_A  (out + 0)
//   rel 2: embed2[src2] += into h_A
//   rel 3: embed3[src3] += into h_B
// ---------------------------------------------------------------------------
__global__ void scatter_kernel(
    const float* __restrict__ e0, const float* __restrict__ e1,
    const float* __restrict__ e2, const float* __restrict__ e3,
    const void* __restrict__ s0, const void* __restrict__ d0,
    const void* __restrict__ s1, const void* __restrict__ d1,
    const void* __restrict__ s2, const void* __restrict__ d2,
    const void* __restrict__ s3, const void* __restrict__ d3,
    float* __restrict__ out, int nE, long long nN)
{
    int g = blockIdx.x * blockDim.x + threadIdx.x;
    int edge = g >> 4;
    int c    = g & 15;
    if (edge >= nE) return;

    const float* emb;
    const void*  sp;
    const void*  dp;
    long long    outOff;
    switch (blockIdx.y) {
        case 0:  emb = e0; sp = s0; dp = d0; outOff = nN * DIM; break;
        case 1:  emb = e1; sp = s1; dp = d1; outOff = 0;        break;
        case 2:  emb = e2; sp = s2; dp = d2; outOff = 0;        break;
        default: emb = e3; sp = s3; dp = d3; outOff = nN * DIM; break;
    }

    const int idx64 = g_idx64;
    long long src = load_idx(sp, edge, idx64);
    long long dst = load_idx(dp, edge, idx64);

    const float4 v =
        *reinterpret_cast<const float4*>(emb + src * DIM + (long long)c * 4);
    float* p = out + outOff + dst * DIM + (long long)c * 4;

    // vector f32 reduction (no return) — sm_90+ red.global.add.v4.f32
    asm volatile("red.global.add.v4.f32 [%0], {%1,%2,%3,%4};"
                 :: "l"(p), "f"(v.x), "f"(v.y), "f"(v.z), "f"(v.w)
                 : "memory");
}

// ---------------------------------------------------------------------------
// epilogue: out = relu(out + bias), float4-vectorized.
// out is [2, N, 16] float4; bias is 16 float4; column chunk = i % 16.
// ---------------------------------------------------------------------------
__global__ void bias_relu_kernel(float4* __restrict__ out,
                                 const float4* __restrict__ bias4, int n4) {
    int i = blockIdx.x * blockDim.x + threadIdx.x;
    if (i >= n4) return;
    float4 v = out[i];
    float4 b = __ldg(&bias4[i & 15]);
    v.x = fmaxf(v.x + b.x, 0.f);
    v.y = fmaxf(v.y + b.y, 0.f);
    v.z = fmaxf(v.z + b.z, 0.f);
    v.w = fmaxf(v.w + b.w, 0.f);
    out[i] = v;
}

// ---------------------------------------------------------------------------
// kernel_launch
// input order (metadata): embed0..embed3, h_bias, src0,dst0, src1,dst1,
//                         src2,dst2, src3,dst3
// ---------------------------------------------------------------------------
extern "C" void kernel_launch(void* const* d_in, const int* in_sizes, int n_in,
                              void* d_out, int out_size) {
    const float* e0 = (const float*)d_in[0];
    const float* e1 = (const float*)d_in[1];
    const float* e2 = (const float*)d_in[2];
    const float* e3 = (const float*)d_in[3];
    const float* bias = (const float*)d_in[4];

    const long long nN = in_sizes[0] / DIM;   // 100000
    const int       nE = in_sizes[5];         // 500000
    const int       n4 = out_size / 4;        // 2*N*16 float4

    float* out = (float*)d_out;
    const int T = 256;

    // 0) detect index width (writes g_idx64; ordered before scatter in-stream)
    probe_kernel<<<1, 32>>>((const unsigned int*)d_in[5]);

    // 1) zero accumulators
    zero_kernel<<<(n4 + T - 1) / T, T>>>((float4*)out, n4);

    // 2) scatter-add all 4 relations (gridDim.y = relation)
    {
        int work = nE * CHUNKS;                  // 8M threads per relation
        dim3 grid((work + T - 1) / T, 4, 1);
        scatter_kernel<<<grid, T>>>(e0, e1, e2, e3,
                                    d_in[5], d_in[6], d_in[7], d_in[8],
                                    d_in[9], d_in[10], d_in[11], d_in[12],
                                    out, nE, nN);
    }

    // 3) bias + relu
    bias_relu_kernel<<<(n4 + T - 1) / T, T>>>((float4*)out,
                                              (const float4*)bias, n4);
}